// round 9
// baseline (speedup 1.0000x reference)
#include <cuda_runtime.h>
#include <cuda_bf16.h>

#define DEPTH        4096
#define NTHREADS     512     /* one thread per 8 samples per row */
#define ROWS_PER_CTA 8       /* processed as 4 interleaved pairs */
#define HKC          0.70710678118654752440f

// Pair-interleaved register-resident wavelet layer.
// Rows are processed two at a time; coefficients for the pair are stored
// interleaved in shared memory (c2[q] = {row_a, row_b}) so each random
// gather is ONE LDS.64 serving both rows (~38% fewer bank-conflict cycles
// than two LDS.32). Next pair's x is prefetched into the just-freed x
// registers (issued after y extraction), overlapping DRAM latency with the
// butterfly + barrier + gather + store of the current pair.
//
// Reference slice map (reproduced exactly, incl. overlapping slices):
//   coeff_lst = [ g[0:256], g[2048:2304], g[1024:1536], g[512:1536], g[256:2304] ]
__global__ __launch_bounds__(NTHREADS, 2)
void wavelet_fused_kernel(const float* __restrict__ x,
                          const float* __restrict__ vec_b,
                          const float* __restrict__ vec_g,
                          const float* __restrict__ vec_s,
                          const int*  __restrict__ perm,
                          float* __restrict__ out)
{
    __shared__ float2 c2[DEPTH];                  // 32 KB, .x=row a, .y=row b

    const int t  = threadIdx.x;
    const int th = t >> 1;                        // thread-pair index

    // ---- persistent broadcast data (amortized over 8 rows) ---------------
    const int  p0 = __ldg(&perm[th]);
    const int  p1 = __ldg(&perm[2048 + th]);
    const int  p2 = __ldg(&perm[1024 + t]);
    const int2 p3 = __ldg(reinterpret_cast<const int2*>(&perm[512 + 2 * t]));
    const int4 p4 = __ldg(reinterpret_cast<const int4*>(&perm[256 + 4 * t]));

    const float  w0 = __ldg(&vec_g[th]);
    const float  w1 = __ldg(&vec_g[2048 + th]);
    const float  w2 = __ldg(&vec_g[1024 + t]);
    const float2 w3 = __ldg(reinterpret_cast<const float2*>(&vec_g[512 + 2 * t]));
    const float4 w4 = __ldg(reinterpret_cast<const float4*>(&vec_g[256 + 4 * t]));

    const float4 bv0 = __ldg(reinterpret_cast<const float4*>(&vec_b[8 * t]));
    const float4 bv1 = __ldg(reinterpret_cast<const float4*>(&vec_b[8 * t + 4]));

    const float H2 = HKC * HKC;
    const float H3 = H2 * HKC;
    const float H4 = H2 * H2;

    const size_t base = (size_t)blockIdx.x * ROWS_PER_CTA * DEPTH;
    const float4* x4  = reinterpret_cast<const float4*>(x + base);
    float4*       o4  = reinterpret_cast<float4*>(out + base);
    const float4* sp4 = reinterpret_cast<const float4*>(vec_s) + 2 * t;

    // prologue: load pair 0 (rows 0 and 1)
    float4 xa0 = __ldcs(&x4[2 * t]);
    float4 xa1 = __ldcs(&x4[2 * t + 1]);
    float4 xb0 = __ldcs(&x4[1024 + 2 * t]);
    float4 xb1 = __ldcs(&x4[1024 + 2 * t + 1]);

    #pragma unroll 1
    for (int k = 0; k < ROWS_PER_CTA / 2; ++k) {
        // ---- y = x * vec_b for both rows (frees the x registers) ---------
        const float ya0 = xa0.x * bv0.x, ya1 = xa0.y * bv0.y;
        const float ya2 = xa0.z * bv0.z, ya3 = xa0.w * bv0.w;
        const float ya4 = xa1.x * bv1.x, ya5 = xa1.y * bv1.y;
        const float ya6 = xa1.z * bv1.z, ya7 = xa1.w * bv1.w;
        const float yb0 = xb0.x * bv0.x, yb1 = xb0.y * bv0.y;
        const float yb2 = xb0.z * bv0.z, yb3 = xb0.w * bv0.w;
        const float yb4 = xb1.x * bv1.x, yb5 = xb1.y * bv1.y;
        const float yb6 = xb1.z * bv1.z, yb7 = xb1.w * bv1.w;

        // ---- prefetch next pair into the same registers ------------------
        if (k + 1 < ROWS_PER_CTA / 2) {
            const float4* xn = x4 + (size_t)(2 * k + 2) * (DEPTH / 4);
            xa0 = __ldcs(&xn[2 * t]);
            xa1 = __ldcs(&xn[2 * t + 1]);
            xb0 = __ldcs(&xn[1024 + 2 * t]);
            xb1 = __ldcs(&xn[1024 + 2 * t + 1]);
        }

        // ---- decomposition butterflies, interleaved stores ---------------
        // d1 (logical 2048+4t+i)
        c2[2048 + 4 * t + 0] = make_float2((ya0 - ya1) * HKC, (yb0 - yb1) * HKC);
        c2[2048 + 4 * t + 1] = make_float2((ya2 - ya3) * HKC, (yb2 - yb3) * HKC);
        c2[2048 + 4 * t + 2] = make_float2((ya4 - ya5) * HKC, (yb4 - yb5) * HKC);
        c2[2048 + 4 * t + 3] = make_float2((ya6 - ya7) * HKC, (yb6 - yb7) * HKC);

        const float s1a0 = ya0 + ya1, s1a1 = ya2 + ya3, s1a2 = ya4 + ya5, s1a3 = ya6 + ya7;
        const float s1b0 = yb0 + yb1, s1b1 = yb2 + yb3, s1b2 = yb4 + yb5, s1b3 = yb6 + yb7;

        // d2 (logical 1024+2t+i)
        c2[1024 + 2 * t + 0] = make_float2((s1a0 - s1a1) * H2, (s1b0 - s1b1) * H2);
        c2[1024 + 2 * t + 1] = make_float2((s1a2 - s1a3) * H2, (s1b2 - s1b3) * H2);

        const float s2a0 = s1a0 + s1a1, s2a1 = s1a2 + s1a3;
        const float s2b0 = s1b0 + s1b1, s2b1 = s1b2 + s1b3;

        // d3 (logical 512+t)
        c2[512 + t] = make_float2((s2a0 - s2a1) * H3, (s2b0 - s2b1) * H3);

        const float s3a  = s2a0 + s2a1;
        const float s3b  = s2b0 + s2b1;
        const float s3ao = __shfl_xor_sync(0xffffffffu, s3a, 1);
        const float s3bo = __shfl_xor_sync(0xffffffffu, s3b, 1);

        if (t & 1)  // odd lane holds hi half: d4 = lo - hi
            c2[256 + th] = make_float2((s3ao - s3a) * H4, (s3bo - s3b) * H4);
        else        // even lane holds lo half: cA4 = lo + hi
            c2[th]       = make_float2((s3a + s3ao) * H4, (s3b + s3bo) * H4);

        __syncthreads();

        // ---- gather: one LDS.64 per index serves both rows ---------------
        const float2 g0  = c2[p0];
        const float2 g1  = c2[p1];
        const float2 g2  = c2[p2];
        const float2 g3x = c2[p3.x];
        const float2 g3y = c2[p3.y];
        const float2 g4x = c2[p4.x];
        const float2 g4y = c2[p4.y];
        const float2 g4z = c2[p4.z];
        const float2 g4w = c2[p4.w];

        const float4 sv0 = __ldg(&sp4[0]);
        const float4 sv1 = __ldg(&sp4[1]);

        // ---- inverse butterfly + store, row a ----------------------------
        {
            const float G0 = w0 * g0.x,  G1 = w1 * g1.x,  G2 = w2 * g2.x;
            const float G3x = w3.x * g3x.x, G3y = w3.y * g3y.x;
            const float r1  = ((t & 1) ? (G0 - G1) : (G0 + G1)) * HKC;
            const float r2a = (r1 + G2) * HKC,  r2b = (r1 - G2) * HKC;
            const float r3a = (r2a + G3x) * HKC, r3b = (r2a - G3x) * HKC;
            const float r3c = (r2b + G3y) * HKC, r3d = (r2b - G3y) * HKC;
            const float G4x = w4.x * g4x.x, G4y = w4.y * g4y.x;
            const float G4z = w4.z * g4z.x, G4w = w4.w * g4w.x;
            float4 o0, o1;
            o0.x = (r3a + G4x) * HKC * sv0.x;  o0.y = (r3a - G4x) * HKC * sv0.y;
            o0.z = (r3b + G4y) * HKC * sv0.z;  o0.w = (r3b - G4y) * HKC * sv0.w;
            o1.x = (r3c + G4z) * HKC * sv1.x;  o1.y = (r3c - G4z) * HKC * sv1.y;
            o1.z = (r3d + G4w) * HKC * sv1.z;  o1.w = (r3d - G4w) * HKC * sv1.w;
            float4* orow = o4 + (size_t)(2 * k) * (DEPTH / 4);
            __stcs(&orow[2 * t],     o0);
            __stcs(&orow[2 * t + 1], o1);
        }

        // ---- inverse butterfly + store, row b ----------------------------
        {
            const float G0 = w0 * g0.y,  G1 = w1 * g1.y,  G2 = w2 * g2.y;
            const float G3x = w3.x * g3x.y, G3y = w3.y * g3y.y;
            const float r1  = ((t & 1) ? (G0 - G1) : (G0 + G1)) * HKC;
            const float r2a = (r1 + G2) * HKC,  r2b = (r1 - G2) * HKC;
            const float r3a = (r2a + G3x) * HKC, r3b = (r2a - G3x) * HKC;
            const float r3c = (r2b + G3y) * HKC, r3d = (r2b - G3y) * HKC;
            const float G4x = w4.x * g4x.y, G4y = w4.y * g4y.y;
            const float G4z = w4.z * g4z.y, G4w = w4.w * g4w.y;
            float4 o0, o1;
            o0.x = (r3a + G4x) * HKC * sv0.x;  o0.y = (r3a - G4x) * HKC * sv0.y;
            o0.z = (r3b + G4y) * HKC * sv0.z;  o0.w = (r3b - G4y) * HKC * sv0.w;
            o1.x = (r3c + G4z) * HKC * sv1.x;  o1.y = (r3c - G4z) * HKC * sv1.y;
            o1.z = (r3d + G4w) * HKC * sv1.z;  o1.w = (r3d - G4w) * HKC * sv1.w;
            float4* orow = o4 + (size_t)(2 * k + 1) * (DEPTH / 4);
            __stcs(&orow[2 * t],     o0);
            __stcs(&orow[2 * t + 1], o1);
        }

        __syncthreads();   // protect c2 against next pair's writes
    }
}

extern "C" void kernel_launch(void* const* d_in, const int* in_sizes, int n_in,
                              void* d_out, int out_size)
{
    const float* x     = (const float*)d_in[0];
    const float* vec_b = (const float*)d_in[1];
    const float* vec_g = (const float*)d_in[2];
    const float* vec_s = (const float*)d_in[3];
    const int*   perm  = (const int*)  d_in[4];
    float* out = (float*)d_out;

    const int batch = in_sizes[0] / DEPTH;            // 8192
    wavelet_fused_kernel<<<batch / ROWS_PER_CTA, NTHREADS>>>(x, vec_b, vec_g, vec_s, perm, out);
}